// round 5
// baseline (speedup 1.0000x reference)
#include <cuda_runtime.h>
#include <cstdint>

#define DINL __device__ __forceinline__

static constexpr int Bsz = 16384;
static constexpr int Iin = 512;
static constexpr int Hd  = 1024;
static constexpr int Od  = 512;

static constexpr int BM = 128, BK = 32;
static constexpr int NSTAGE = 3;
static constexpr uint32_t A_BYTES     = BM * BK * 4;      // 16KB
static constexpr uint32_t STAGE_BYTES = 2 * A_BYTES;      // 32KB (A tile + B tile)
static constexpr uint32_t SMEM_BYTES  = 1024 + NSTAGE * STAGE_BYTES;  // 97.25KB

// ============================ PTX helpers ============================

DINL uint32_t smem_u32(const void* p) {
    uint32_t a;
    asm("{ .reg .u64 t; cvta.to.shared.u64 t, %1; cvt.u32.u64 %0, t; }" : "=r"(a) : "l"(p));
    return a;
}

DINL void cp_async16(uint32_t dst_smem, const float* src) {
    asm volatile("cp.async.cg.shared.global [%0], [%1], 16;" :: "r"(dst_smem), "l"(src) : "memory");
}
DINL void cp_commit() { asm volatile("cp.async.commit_group;" ::: "memory"); }
template <int N> DINL void cp_wait_group() { asm volatile("cp.async.wait_group %0;" :: "n"(N) : "memory"); }

DINL void ldsm_x4(uint32_t* r, uint32_t addr) {
    asm volatile("ldmatrix.sync.aligned.m8n8.x4.shared.b16 {%0,%1,%2,%3}, [%4];"
                 : "=r"(r[0]), "=r"(r[1]), "=r"(r[2]), "=r"(r[3]) : "r"(addr));
}

DINL void cvt_tf32(uint32_t& x) { asm("cvt.rna.tf32.f32 %0, %0;" : "+r"(x)); }

DINL void mma_tf32(float* c, const uint32_t* a, const uint32_t* b) {
    asm volatile(
        "mma.sync.aligned.m16n8k8.row.col.f32.tf32.tf32.f32 "
        "{%0,%1,%2,%3}, {%4,%5,%6,%7}, {%8,%9}, {%0,%1,%2,%3};"
        : "+f"(c[0]), "+f"(c[1]), "+f"(c[2]), "+f"(c[3])
        : "r"(a[0]), "r"(a[1]), "r"(a[2]), "r"(a[3]), "r"(b[0]), "r"(b[1]));
}

DINL float sigmoidf_(float x) { return 1.0f / (1.0f + __expf(-x)); }
DINL float tanhf_(float x) {
    float e = __expf(2.0f * x);          // saturates correctly at +/-inf
    return 1.0f - 2.0f / (e + 1.0f);
}

// XOR-swizzled byte offset for element group (row, cg) in a [rows x 32f] tile
DINL uint32_t swz(int r, int cg) {
    return (uint32_t)(r * 128) + (uint32_t)((cg ^ (r & 7)) << 4);
}

// ============================ Kernel A: fused gates ============================
// G[b, g*32+hc] = sum_k inp[b,k] Wx[g, n0+hc, k] + sum_k h[b,k] Wh[g, n0+hc, k]
// Epilogue fuses bias + sigmoid/tanh + c update + h_new store.

__global__ __launch_bounds__(256, 2)
void lstm_gates_kernel(const float* __restrict__ inp, const float* __restrict__ hprev,
                       const float* __restrict__ cprev, const float* __restrict__ Wx,
                       const float* __restrict__ bx, const float* __restrict__ Wh,
                       float* __restrict__ hnew)
{
    extern __shared__ char dynsmem[];
    const uint32_t raw = smem_u32(dynsmem);
    const uint32_t sb  = (raw + 1023u) & ~1023u;
    float* sf = (float*)(dynsmem + (sb - raw));

    const int tid  = threadIdx.x;
    const int lane = tid & 31, wid = tid >> 5;
    const int n0 = blockIdx.x * 32;    // h-column tile base
    const int b0 = blockIdx.y * BM;    // batch tile base

    const int wm = wid & 1, wn = wid >> 1;     // 2 x 4 warp grid
    const int m0 = wm * 64, n0w = wn * 32;

    const int tIdx = lane >> 3, rIT = lane & 7;
    const int aHi = tIdx >> 1, bLoP = tIdx & 1;
    const int gid = lane >> 2, tig = lane & 3;

    uint32_t rowoffA[4], rowoffB[2];
    #pragma unroll
    for (int im = 0; im < 4; ++im)
        rowoffA[im] = (uint32_t)(m0 + im * 16 + ((tIdx & 1) << 3) + rIT) * 128u;
    #pragma unroll
    for (int p = 0; p < 2; ++p)
        rowoffB[p] = (uint32_t)(n0w + p * 16 + ((tIdx >> 1) << 3) + rIT) * 128u;

    float acc[4][4][4];
    #pragma unroll
    for (int i = 0; i < 4; ++i)
        #pragma unroll
        for (int j = 0; j < 4; ++j)
            #pragma unroll
            for (int c = 0; c < 4; ++c) acc[i][j][c] = 0.0f;

    constexpr int NC = (Iin + Hd) / BK;  // 48 K-chunks

    auto load_chunk = [&](int kc, int s) {
        const uint32_t Ab = sb + (uint32_t)s * STAGE_BYTES;
        const uint32_t Bb = Ab + A_BYTES;
        const float *asrc, *wsrc; int astr, wstr;
        if (kc < Iin / BK) { asrc = inp + kc * BK;                astr = Iin;
                             wsrc = Wx  + kc * BK;                wstr = Iin; }
        else               { asrc = hprev + (kc - Iin/BK) * BK;   astr = Hd;
                             wsrc = Wh    + (kc - Iin/BK) * BK;   wstr = Hd; }
        #pragma unroll
        for (int q = tid; q < 1024; q += 256) {            // A: 128 rows x 8 groups
            int r = q >> 3, cg = q & 7;
            cp_async16(Ab + swz(r, cg), asrc + (long)(b0 + r) * astr + cg * 4);
        }
        #pragma unroll
        for (int q = tid; q < 1024; q += 256) {            // B: 4 gates x 32 n-rows
            int r = q >> 3, cg = q & 7;
            int g = r >> 5, col = n0 + (r & 31);
            cp_async16(Bb + swz(r, cg), wsrc + (long)(g * Hd + col) * wstr + cg * 4);
        }
    };

    load_chunk(0, 0); cp_commit();
    load_chunk(1, 1); cp_commit();

    for (int k = 0; k < NC; ++k) {
        if (k < NC - 1) cp_wait_group<1>(); else cp_wait_group<0>();
        __syncthreads();
        if (k + 2 < NC) { load_chunk(k + 2, (k + 2) % NSTAGE); cp_commit(); }

        const uint32_t Ab = sb + (uint32_t)(k % NSTAGE) * STAGE_BYTES;
        const uint32_t Bb = Ab + A_BYTES;
        #pragma unroll
        for (int ks = 0; ks < 4; ++ks) {
            uint32_t a[4][4], b[2][4];
            #pragma unroll
            for (int im = 0; im < 4; ++im)
                ldsm_x4(a[im], Ab + rowoffA[im] + (uint32_t)(((2 * ks + aHi) ^ rIT) << 4));
            #pragma unroll
            for (int p = 0; p < 2; ++p)
                ldsm_x4(b[p], Bb + rowoffB[p] + (uint32_t)(((2 * ks + bLoP) ^ rIT) << 4));
            #pragma unroll
            for (int im = 0; im < 4; ++im)
                #pragma unroll
                for (int c = 0; c < 4; ++c) cvt_tf32(a[im][c]);
            #pragma unroll
            for (int p = 0; p < 2; ++p)
                #pragma unroll
                for (int c = 0; c < 4; ++c) cvt_tf32(b[p][c]);
            #pragma unroll
            for (int im = 0; im < 4; ++im)
                #pragma unroll
                for (int in = 0; in < 4; ++in)
                    mma_tf32(acc[im][in], a[im], &b[in >> 1][(in & 1) * 2]);
        }
    }
    __syncthreads();

    // ---- stage accumulators to smem (per-warp 64x32 region, pitch 33) ----
    const int wreg = wid * (64 * 33);
    #pragma unroll
    for (int im = 0; im < 4; ++im)
        #pragma unroll
        for (int in = 0; in < 4; ++in) {
            int r0 = im * 16 + gid, c0 = in * 8 + 2 * tig;
            sf[wreg + r0 * 33 + c0]           = acc[im][in][0];
            sf[wreg + r0 * 33 + c0 + 1]       = acc[im][in][1];
            sf[wreg + (r0 + 8) * 33 + c0]     = acc[im][in][2];
            sf[wreg + (r0 + 8) * 33 + c0 + 1] = acc[im][in][3];
        }
    __syncthreads();

    // ---- fused LSTM elementwise ----
    const int hc = tid & 31;
    const int hcol = n0 + hc;
    const float b_i = bx[hcol], b_o = bx[Hd + hcol], b_f = bx[2 * Hd + hcol];
    #pragma unroll
    for (int it = 0; it < 16; ++it) {
        int q = it * 256 + tid;
        int r = q >> 5;                 // 0..127 batch row within tile
        int rl = r & 63, rh = r >> 6;
        float gi = sf[((0 << 1) | rh) * 2112 + rl * 33 + hc] + b_i;
        float go = sf[((1 << 1) | rh) * 2112 + rl * 33 + hc] + b_o;
        float gf = sf[((2 << 1) | rh) * 2112 + rl * 33 + hc] + b_f;
        float gz = sf[((3 << 1) | rh) * 2112 + rl * 33 + hc];       // z bias = 0
        float cv = cprev[(long)(b0 + r) * Hd + hcol];
        float cn = sigmoidf_(gi) * tanhf_(gz) + sigmoidf_(gf) * cv;
        hnew[(long)(b0 + r) * Hd + hcol] = sigmoidf_(go) * tanhf_(cn);
    }
}

// ============================ Kernel B: output projection ============================
// out[b, o] = sum_k hnew[b,k] * Wout[o,k] + bout[o]

__global__ __launch_bounds__(256, 2)
void out_proj_kernel(const float* __restrict__ hn, const float* __restrict__ Wout,
                     const float* __restrict__ bout, float* __restrict__ outp)
{
    extern __shared__ char dynsmem[];
    const uint32_t raw = smem_u32(dynsmem);
    const uint32_t sb  = (raw + 1023u) & ~1023u;
    float* sf = (float*)(dynsmem + (sb - raw));

    const int tid  = threadIdx.x;
    const int lane = tid & 31, wid = tid >> 5;
    const int n1 = blockIdx.x * 128;   // out-column tile base
    const int b0 = blockIdx.y * BM;

    const int wm = wid & 1, wn = wid >> 1;
    const int m0 = wm * 64, n0w = wn * 32;

    const int tIdx = lane >> 3, rIT = lane & 7;
    const int aHi = tIdx >> 1, bLoP = tIdx & 1;
    const int gid = lane >> 2, tig = lane & 3;

    uint32_t rowoffA[4], rowoffB[2];
    #pragma unroll
    for (int im = 0; im < 4; ++im)
        rowoffA[im] = (uint32_t)(m0 + im * 16 + ((tIdx & 1) << 3) + rIT) * 128u;
    #pragma unroll
    for (int p = 0; p < 2; ++p)
        rowoffB[p] = (uint32_t)(n0w + p * 16 + ((tIdx >> 1) << 3) + rIT) * 128u;

    float acc[4][4][4];
    #pragma unroll
    for (int i = 0; i < 4; ++i)
        #pragma unroll
        for (int j = 0; j < 4; ++j)
            #pragma unroll
            for (int c = 0; c < 4; ++c) acc[i][j][c] = 0.0f;

    constexpr int NC = Hd / BK;  // 32

    auto load_chunk = [&](int kc, int s) {
        const uint32_t Ab = sb + (uint32_t)s * STAGE_BYTES;
        const uint32_t Bb = Ab + A_BYTES;
        #pragma unroll
        for (int q = tid; q < 1024; q += 256) {
            int r = q >> 3, cg = q & 7;
            cp_async16(Ab + swz(r, cg), hn + (long)(b0 + r) * Hd + kc * BK + cg * 4);
        }
        #pragma unroll
        for (int q = tid; q < 1024; q += 256) {
            int r = q >> 3, cg = q & 7;
            cp_async16(Bb + swz(r, cg), Wout + (long)(n1 + r) * Hd + kc * BK + cg * 4);
        }
    };

    load_chunk(0, 0); cp_commit();
    load_chunk(1, 1); cp_commit();

    for (int k = 0; k < NC; ++k) {
        if (k < NC - 1) cp_wait_group<1>(); else cp_wait_group<0>();
        __syncthreads();
        if (k + 2 < NC) { load_chunk(k + 2, (k + 2) % NSTAGE); cp_commit(); }

        const uint32_t Ab = sb + (uint32_t)(k % NSTAGE) * STAGE_BYTES;
        const uint32_t Bb = Ab + A_BYTES;
        #pragma unroll
        for (int ks = 0; ks < 4; ++ks) {
            uint32_t a[4][4], b[2][4];
            #pragma unroll
            for (int im = 0; im < 4; ++im)
                ldsm_x4(a[im], Ab + rowoffA[im] + (uint32_t)(((2 * ks + aHi) ^ rIT) << 4));
            #pragma unroll
            for (int p = 0; p < 2; ++p)
                ldsm_x4(b[p], Bb + rowoffB[p] + (uint32_t)(((2 * ks + bLoP) ^ rIT) << 4));
            #pragma unroll
            for (int im = 0; im < 4; ++im)
                #pragma unroll
                for (int c = 0; c < 4; ++c) cvt_tf32(a[im][c]);
            #pragma unroll
            for (int p = 0; p < 2; ++p)
                #pragma unroll
                for (int c = 0; c < 4; ++c) cvt_tf32(b[p][c]);
            #pragma unroll
            for (int im = 0; im < 4; ++im)
                #pragma unroll
                for (int in = 0; in < 4; ++in)
                    mma_tf32(acc[im][in], a[im], &b[in >> 1][(in & 1) * 2]);
        }
    }
    __syncthreads();

    const int wreg = wid * (64 * 33);
    #pragma unroll
    for (int im = 0; im < 4; ++im)
        #pragma unroll
        for (int in = 0; in < 4; ++in) {
            int r0 = im * 16 + gid, c0 = in * 8 + 2 * tig;
            sf[wreg + r0 * 33 + c0]           = acc[im][in][0];
            sf[wreg + r0 * 33 + c0 + 1]       = acc[im][in][1];
            sf[wreg + (r0 + 8) * 33 + c0]     = acc[im][in][2];
            sf[wreg + (r0 + 8) * 33 + c0 + 1] = acc[im][in][3];
        }
    __syncthreads();

    const int cc = tid & 127;
    const float bb = bout[n1 + cc];
    #pragma unroll
    for (int it = 0; it < 64; ++it) {
        int r = it * 2 + (tid >> 7);
        int rl = r & 63, rh = r >> 6;
        int w2 = ((cc >> 5) << 1) | rh;
        outp[(long)(b0 + r) * Od + n1 + cc] = sf[w2 * 2112 + rl * 33 + (cc & 31)] + bb;
    }
}

// ============================ launch ============================

extern "C" void kernel_launch(void* const* d_in, const int* in_sizes, int n_in,
                              void* d_out, int out_size) {
    const float* inp  = (const float*)d_in[0];
    const float* h    = (const float*)d_in[1];
    const float* c    = (const float*)d_in[2];
    const float* Wx   = (const float*)d_in[3];
    const float* bx   = (const float*)d_in[4];
    const float* Wh   = (const float*)d_in[5];
    const float* Wout = (const float*)d_in[6];
    const float* bout = (const float*)d_in[7];
    float* out = (float*)d_out;

    // output tuple (out, h_new) flattened: out[B,O] then h_new[B,H]
    float* hnew = out + (long)Bsz * Od;

    cudaFuncSetAttribute(lstm_gates_kernel, cudaFuncAttributeMaxDynamicSharedMemorySize, SMEM_BYTES);
    cudaFuncSetAttribute(out_proj_kernel,  cudaFuncAttributeMaxDynamicSharedMemorySize, SMEM_BYTES);

    lstm_gates_kernel<<<dim3(Hd / 32, Bsz / BM), 256, SMEM_BYTES>>>(inp, h, c, Wx, bx, Wh, hnew);
    out_proj_kernel<<<dim3(Od / 128, Bsz / BM), 256, SMEM_BYTES>>>(hnew, Wout, bout, out);
}